// round 13
// baseline (speedup 1.0000x reference)
#include <cuda_runtime.h>

// CLUBv2: mi = BETA * sum_d Var_d(y[:, d])
// y: [1024, 256] fp32 row-major. Output: 1 fp32 scalar.
//
//   mi = ( sum_d E[y^2]_d - sum_d mu_d^2 ) * BETA
//       = sum_d ( Q_d/N - mu_d^2 ) * BETA
//
// Champion family (6.62-6.66us x3). R13 delta: per-column (s,q) stored
// together as float2 -> NO Q shuffle tree / smem / t0 Q-work on the
// pre-ticket critical path (loads -> 1 STG.64 -> bar -> ticket), and the
// tail reduces one combined value per thread. Disjoint plain stores (no
// data atomics), ONE acq_rel ticket per block, fixed-order reduction ->
// bit-deterministic fp32.

#define N_ROWS 1024
#define N_COLS 256
#define GRID   32
#define ROWS_PER_BLOCK (N_ROWS / GRID)   // 32
#define BETA_F 0.001f

__device__ float2       g_p[GRID * N_COLS];   // per-block (sum, sumsq) (64KB)
__device__ unsigned int g_ticket = 0;
// g_p fully overwritten every launch; winner resets g_ticket -> every
// graph replay identical. Deterministic.

__device__ __forceinline__ unsigned int atom_add_acq_rel(unsigned int* addr,
                                                         unsigned int v) {
    unsigned int old;
    asm volatile("atom.acq_rel.gpu.global.add.u32 %0, [%1], %2;"
                 : "=r"(old) : "l"(addr), "r"(v) : "memory");
    return old;
}

__device__ __forceinline__ float2 ldcg_f2(const float2* a) {
    float2 r;
    asm volatile("ld.global.cg.v2.f32 {%0, %1}, [%2];"
                 : "=f"(r.x), "=f"(r.y) : "l"(a));
    return r;
}

__global__ void __launch_bounds__(N_COLS, 1)
club_var_kernel(const float* __restrict__ y, float* __restrict__ out) {
    const int t    = threadIdx.x;   // column index 0..255
    const int b    = blockIdx.x;
    const int lane = t & 31;
    const int warp = t >> 5;

    // Phase 1: 32 rows per block per column, coalesced scalar loads,
    // fully unrolled -> deep MLP, one memory-latency exposure.
    float s = 0.0f, q = 0.0f;
    const float* p = y + (size_t)b * ROWS_PER_BLOCK * N_COLS + t;
    #pragma unroll
    for (int r = 0; r < ROWS_PER_BLOCK; ++r) {
        float v = p[r * N_COLS];
        s += v;
        q = fmaf(v, v, q);
    }

    // ONE disjoint STG.64 carries both partials. No shuffles, no smem,
    // no extra t0 work before the ticket.
    float2 sq; sq.x = s; sq.y = q;
    asm volatile("st.global.cg.v2.f32 [%0], {%1, %2};"
                 :: "l"(&g_p[b * N_COLS + t]), "f"(sq.x), "f"(sq.y)
                 : "memory");

    // Ticket: bar.sync orders this block's stores before t0's gpu-scope
    // acq_rel release; winner's acquire sees all 32 blocks' stores.
    __shared__ bool is_last;
    __syncthreads();
    if (t == 0)
        is_last = (atom_add_acq_rel(&g_ticket, 1u) == (unsigned)(GRID - 1));
    __syncthreads();

    if (is_last) {
        // Tail: 64KB from L2, coalesced (warp instr = 2 x 128B lines).
        // Thread t sums column t across 32 blocks: 4 independent
        // accumulator pairs (max serial chain 8), fixed order.
        float s0 = 0.f, s1 = 0.f, s2 = 0.f, s3 = 0.f;
        float q0 = 0.f, q1 = 0.f, q2 = 0.f, q3 = 0.f;
        #pragma unroll
        for (int bb = 0; bb < GRID; bb += 4) {
            float2 v0 = ldcg_f2(&g_p[(bb + 0) * N_COLS + t]);
            float2 v1 = ldcg_f2(&g_p[(bb + 1) * N_COLS + t]);
            float2 v2 = ldcg_f2(&g_p[(bb + 2) * N_COLS + t]);
            float2 v3 = ldcg_f2(&g_p[(bb + 3) * N_COLS + t]);
            s0 += v0.x; q0 += v0.y;
            s1 += v1.x; q1 += v1.y;
            s2 += v2.x; q2 += v2.y;
            s3 += v3.x; q3 += v3.y;
        }
        const float S = (s0 + s1) + (s2 + s3);
        const float Q = (q0 + q1) + (q2 + q3);

        const float invN = 1.0f / (float)N_ROWS;
        const float mu = S * invN;
        // Per-column contribution: Var_d = Q_d/N - mu_d^2. One value per
        // thread -> one fixed-order reduction tree.
        float acc = fmaf(-mu, mu, Q * invN);

        #pragma unroll
        for (int off = 16; off > 0; off >>= 1)
            acc += __shfl_down_sync(0xFFFFFFFFu, acc, off);
        __shared__ float wsum[8];
        if (lane == 0) wsum[warp] = acc;
        __syncthreads();

        if (warp == 0) {
            float v = (lane < 8) ? wsum[lane] : 0.0f;
            #pragma unroll
            for (int off = 4; off > 0; off >>= 1)
                v += __shfl_down_sync(0xFFFFFFFFu, v, off);
            if (lane == 0) {
                out[0] = v * BETA_F;
                g_ticket = 0;   // reset for next graph replay
            }
        }
    }
}

extern "C" void kernel_launch(void* const* d_in, const int* in_sizes, int n_in,
                              void* d_out, int out_size) {
    (void)in_sizes; (void)n_in; (void)out_size;
    const float* y = (const float*)d_in[0];
    float* out = (float*)d_out;
    club_var_kernel<<<GRID, N_COLS>>>(y, out);
}